// round 15
// baseline (speedup 1.0000x reference)
#include <cuda_runtime.h>
#include <cuda_fp16.h>

// L0-L2 quad tables: per level/plane/cell, 4 bilinear corners x 2 feat packed
// as 8 fp16 = 16B = one LDG.128. s = {128,256,512}; offsets 0/49152/245760.
#define NQUAD3_TOTAL 1032192
__device__ uint4 g_quads[NQUAD3_TOTAL];

// L3 pair table: per plane/row j/cell i: cells (i, min(i+1,1023)), 2 feat fp16
// each -> 8B = one LDG.64. Bilinear needs rows j and j+1 -> 2 fetches = 16B.
// 3 x 1024 x 1024 x 8B = 25.2 MB (vs 50.3 MB as quads).
#define NPAIR3_TOTAL 3145728
__device__ uint2 g_pairs3[NPAIR3_TOTAL];

__global__ __launch_bounds__(256) void build_quads_kernel(const float* __restrict__ table)
{
    int t = blockIdx.x * blockDim.x + threadIdx.x;
    if (t >= NQUAD3_TOTAL) return;

    int s, off, fac;
    if      (t < 49152)   { s = 128;  off = 0;       fac = 8; }
    else if (t < 245760)  { s = 256;  off = 49152;   fac = 4; }
    else                  { s = 512;  off = 245760;  fac = 2; }

    int r = t - off;
    int per_plane = s * s;
    int pl = r / per_plane;
    int r2 = r - pl * per_plane;
    int j  = r2 / s;
    int i  = r2 - j * s;

    int i0 = min(i * fac,       1023);
    int i1 = min((i + 1) * fac, 1023);
    int j0 = min(j * fac,       1023);
    int j1 = min((j + 1) * fac, 1023);

    const float2* __restrict__ tab = (const float2*)table + (size_t)pl * (1024 * 1024);
    float2 v00 = tab[j0 * 1024 + i0];
    float2 v10 = tab[j0 * 1024 + i1];
    float2 v01 = tab[j1 * 1024 + i0];
    float2 v11 = tab[j1 * 1024 + i1];

    __half2 h0 = __floats2half2_rn(v00.x, v00.y);
    __half2 h1 = __floats2half2_rn(v10.x, v10.y);
    __half2 h2 = __floats2half2_rn(v01.x, v01.y);
    __half2 h3 = __floats2half2_rn(v11.x, v11.y);

    uint4 q;
    q.x = *reinterpret_cast<unsigned*>(&h0);
    q.y = *reinterpret_cast<unsigned*>(&h1);
    q.z = *reinterpret_cast<unsigned*>(&h2);
    q.w = *reinterpret_cast<unsigned*>(&h3);
    g_quads[t] = q;
}

__global__ __launch_bounds__(256) void build_pairs3_kernel(const float* __restrict__ table)
{
    int t = blockIdx.x * blockDim.x + threadIdx.x;
    if (t >= NPAIR3_TOTAL) return;

    int pl  = t >> 20;
    int rem = t & 1048575;
    int j   = rem >> 10;
    int i   = rem & 1023;

    const float2* __restrict__ tab = (const float2*)table + (size_t)pl * (1024 * 1024);
    float2 a = tab[j * 1024 + i];
    float2 b = tab[j * 1024 + min(i + 1, 1023)];

    __half2 ha = __floats2half2_rn(a.x, a.y);
    __half2 hb = __floats2half2_rn(b.x, b.y);

    uint2 p;
    p.x = *reinterpret_cast<unsigned*>(&ha);
    p.y = *reinterpret_cast<unsigned*>(&hb);
    g_pairs3[t] = p;
}

// NOTE: no min-blocks clause — forcing regs<=40 measured ~1.8x slower.
__global__ __launch_bounds__(256) void triplane_kernel(
    const float* __restrict__ positions,
    float* __restrict__ out,
    int B)
{
    __shared__ float4 sbuf[8][32 * 9];   // per-warp staging, stride-9 padded

    const int warp = threadIdx.x >> 5;
    const int lane = threadIdx.x & 31;

    const int blockStart = blockIdx.x * 256;
    int b  = blockStart + threadIdx.x;
    int bc = b < B ? b : (B - 1);        // clamp so loads stay in-bounds

    float pos[3];
    pos[0] = positions[3 * bc + 0];
    pos[1] = positions[3 * bc + 1];
    pos[2] = positions[3 * bc + 2];

    const int S[3]    = {128, 256, 512};
    const int QOFF[3] = {0, 49152, 245760};

    // Precompute fractions and gather indices (ALU only).
    float frac[4][3];
    int   qix[3][3];       // L0..L2 quad indices
    int   pix[3][2];       // L3 pair indices (rows j, j+1 clamped)
    #pragma unroll
    for (int L = 0; L < 3; L++) {
        const int s = S[L];
        const float sm1 = (float)s - 1.0f;
        int g[3];
        #pragma unroll
        for (int d = 0; d < 3; d++) {
            float x  = fmaf(pos[d], sm1, 0.5f);
            float gf = floorf(x);
            g[d] = (int)gf;
            frac[L][d] = x - gf;
        }
        #pragma unroll
        for (int pl = 0; pl < 3; pl++) {
            const int a1 = (pl + 1) % 3;   // c0=[0,1,2], c1=[1,2,0]
            qix[L][pl] = QOFF[L] + (pl * s + g[a1]) * s + g[pl];
        }
    }
    {
        int g[3];
        #pragma unroll
        for (int d = 0; d < 3; d++) {
            float x  = fmaf(pos[d], 1023.0f, 0.5f);
            float gf = floorf(x);
            g[d] = (int)gf;
            frac[3][d] = x - gf;
        }
        #pragma unroll
        for (int pl = 0; pl < 3; pl++) {
            const int a1 = (pl + 1) % 3;
            int j0 = g[a1];
            int j1 = min(j0 + 1, 1023);
            pix[pl][0] = (pl << 20) + (j0 << 10) + g[pl];
            pix[pl][1] = (pl << 20) + (j1 << 10) + g[pl];
        }
    }

    // Staggered pipeline over L0-L2 (proven R10 structure); L3's 6 LDG.64
    // are prefetched at the L2 consumption slot, consumed straight-line after.
    uint4 qcur[3], qnext[3];
    uint2 p3[3][2];

    #pragma unroll
    for (int pl = 0; pl < 3; pl++)
        qcur[pl] = __ldg(&g_quads[qix[0][pl]]);

    #pragma unroll
    for (int L = 0; L < 3; L++) {
        if (L < 2) {
            #pragma unroll
            for (int pl = 0; pl < 3; pl++)
                qnext[pl] = __ldg(&g_quads[qix[L + 1][pl]]);
        } else {
            #pragma unroll
            for (int pl = 0; pl < 3; pl++) {
                p3[pl][0] = __ldg(&g_pairs3[pix[pl][0]]);
                p3[pl][1] = __ldg(&g_pairs3[pix[pl][1]]);
            }
        }

        float acc[3][2];
        #pragma unroll
        for (int pl = 0; pl < 3; pl++) {
            const int a1 = (pl + 1) % 3;
            const float f0 = frac[L][pl];
            const float f1 = frac[L][a1];
            uint4 qq = qcur[pl];
            float2 c00 = __half22float2(*reinterpret_cast<__half2*>(&qq.x));
            float2 c10 = __half22float2(*reinterpret_cast<__half2*>(&qq.y));
            float2 c01 = __half22float2(*reinterpret_cast<__half2*>(&qq.z));
            float2 c11 = __half22float2(*reinterpret_cast<__half2*>(&qq.w));

            const float w0 = 1.0f - f0;
            float l0x = fmaf(w0, c00.x, f0 * c10.x);
            float l0y = fmaf(w0, c00.y, f0 * c10.y);
            float l1x = fmaf(w0, c01.x, f0 * c11.x);
            float l1y = fmaf(w0, c01.y, f0 * c11.y);

            const float w1 = 1.0f - f1;
            acc[pl][0] = fmaf(w1, l0x, f1 * l1x);
            acc[pl][1] = fmaf(w1, l0y, f1 * l1y);
        }

        const float pr0 = acc[0][0] * acc[1][0] * acc[2][0];
        const float pr1 = acc[0][1] * acc[1][1] * acc[2][1];

        sbuf[warp][lane * 9 + L * 2 + 0] =
            make_float4(acc[0][0], acc[0][1], acc[1][0], acc[1][1]);
        sbuf[warp][lane * 9 + L * 2 + 1] =
            make_float4(acc[2][0], acc[2][1], pr0, pr1);

        if (L < 2) {
            #pragma unroll
            for (int pl = 0; pl < 3; pl++)
                qcur[pl] = qnext[pl];
        }
    }

    // L3 consumption (straight-line, no branch mixing with the quad path).
    {
        float acc[3][2];
        #pragma unroll
        for (int pl = 0; pl < 3; pl++) {
            const int a1 = (pl + 1) % 3;
            const float f0 = frac[3][pl];
            const float f1 = frac[3][a1];
            uint2 r0 = p3[pl][0];
            uint2 r1 = p3[pl][1];
            float2 c00 = __half22float2(*reinterpret_cast<__half2*>(&r0.x));
            float2 c10 = __half22float2(*reinterpret_cast<__half2*>(&r0.y));
            float2 c01 = __half22float2(*reinterpret_cast<__half2*>(&r1.x));
            float2 c11 = __half22float2(*reinterpret_cast<__half2*>(&r1.y));

            const float w0 = 1.0f - f0;
            float l0x = fmaf(w0, c00.x, f0 * c10.x);
            float l0y = fmaf(w0, c00.y, f0 * c10.y);
            float l1x = fmaf(w0, c01.x, f0 * c11.x);
            float l1y = fmaf(w0, c01.y, f0 * c11.y);

            const float w1 = 1.0f - f1;
            acc[pl][0] = fmaf(w1, l0x, f1 * l1x);
            acc[pl][1] = fmaf(w1, l0y, f1 * l1y);
        }

        const float pr0 = acc[0][0] * acc[1][0] * acc[2][0];
        const float pr1 = acc[0][1] * acc[1][1] * acc[2][1];

        sbuf[warp][lane * 9 + 6] =
            make_float4(acc[0][0], acc[0][1], acc[1][0], acc[1][1]);
        sbuf[warp][lane * 9 + 7] =
            make_float4(acc[2][0], acc[2][1], pr0, pr1);
    }

    __syncwarp();

    // Coalesced, warp-scoped store phase; evict-first so the 256 MB output
    // stream does not evict the (now fully L2-resident) 41.5 MB tables.
    const int warpStart = blockStart + warp * 32;
    int vcount = B - warpStart;
    if (vcount > 32) vcount = 32;
    const int nf4 = vcount * 8;
    float4* __restrict__ of4 = (float4*)out + (size_t)warpStart * 8;

    #pragma unroll
    for (int it = 0; it < 8; it++) {
        int w4 = lane + it * 32;
        if (w4 < nf4) {
            int p  = w4 >> 3;
            int jj = w4 & 7;
            __stcs(&of4[w4], sbuf[warp][p * 9 + jj]);
        }
    }
}

extern "C" void kernel_launch(void* const* d_in, const int* in_sizes, int n_in,
                              void* d_out, int out_size) {
    const float* positions = (const float*)d_in[0];
    const float* table     = (const float*)d_in[1];
    float*       out       = (float*)d_out;

    int B = in_sizes[0] / 3;
    const int T = 256;

    build_quads_kernel<<<(NQUAD3_TOTAL + T - 1) / T, T>>>(table);
    build_pairs3_kernel<<<(NPAIR3_TOTAL + T - 1) / T, T>>>(table);
    triplane_kernel<<<(B + T - 1) / T, T>>>(positions, out, B);
}

// round 16
// speedup vs baseline: 1.3331x; 1.3331x over previous
#include <cuda_runtime.h>
#include <cuda_fp16.h>

// Quad tables: per level, per plane, per (i,j) cell: the 4 bilinear corners
// (v00,v10,v01,v11) x 2 features, packed as 8 fp16 = 16 bytes = one LDG.128.
// Levels s = {128,256,512,1024}, entries = 3*s*s each.
// Quad offsets: L0=0, L1=49152, L2=245760, L3=1032192, total 4177920 (66.8 MB).
#define NQUAD_TOTAL 4177920
__device__ uint4 g_quads[NQUAD_TOTAL];

// Build kernel: all level sizes are powers of two, so every division/modulo
// is a shift/mask (the runtime-division version measured issue=53%, alu=26%
// -> ALU-bound at 21us; this version should run at the memory floor).
__global__ __launch_bounds__(256) void build_quads_kernel(const float* __restrict__ table)
{
    int t = blockIdx.x * blockDim.x + threadIdx.x;
    if (t >= NQUAD_TOTAL) return;

    int ls, off, fs;   // ls = log2(s), fs = log2(fac) = 10 - ls
    if      (t < 49152)   { ls = 7;  off = 0;       fs = 3; }
    else if (t < 245760)  { ls = 8;  off = 49152;   fs = 2; }
    else if (t < 1032192) { ls = 9;  off = 245760;  fs = 1; }
    else                  { ls = 10; off = 1032192; fs = 0; }

    int r  = t - off;
    int pl = r >> (2 * ls);
    int r2 = r & ((1 << (2 * ls)) - 1);
    int j  = r2 >> ls;
    int i  = r2 & ((1 << ls) - 1);

    int i0 = min(i << fs,       1023);
    int i1 = min((i + 1) << fs, 1023);
    int j0 = min(j << fs,       1023);
    int j1 = min((j + 1) << fs, 1023);

    const float2* __restrict__ tab = (const float2*)table + (pl << 20);
    float2 v00 = tab[(j0 << 10) + i0];
    float2 v10 = tab[(j0 << 10) + i1];
    float2 v01 = tab[(j1 << 10) + i0];
    float2 v11 = tab[(j1 << 10) + i1];

    __half2 h0 = __floats2half2_rn(v00.x, v00.y);
    __half2 h1 = __floats2half2_rn(v10.x, v10.y);
    __half2 h2 = __floats2half2_rn(v01.x, v01.y);
    __half2 h3 = __floats2half2_rn(v11.x, v11.y);

    uint4 q;
    q.x = *reinterpret_cast<unsigned*>(&h0);
    q.y = *reinterpret_cast<unsigned*>(&h1);
    q.z = *reinterpret_cast<unsigned*>(&h2);
    q.w = *reinterpret_cast<unsigned*>(&h3);
    g_quads[t] = q;
}

// Main kernel: FROZEN at the R10 structure (191 us main, the measured local
// optimum). Staggered 2-deep pipeline, 3 gathers per group, per-warp smem
// store staging, no block barrier, no min-blocks clause (regs<=40 squeeze
// measured ~1.8x slower).
__global__ __launch_bounds__(256) void triplane_kernel(
    const float* __restrict__ positions,
    float* __restrict__ out,
    int B)
{
    __shared__ float4 sbuf[8][32 * 9];   // per-warp staging, stride-9 padded

    const int warp = threadIdx.x >> 5;
    const int lane = threadIdx.x & 31;

    const int blockStart = blockIdx.x * 256;
    int b  = blockStart + threadIdx.x;
    int bc = b < B ? b : (B - 1);        // clamp so loads stay in-bounds

    float pos[3];
    pos[0] = positions[3 * bc + 0];
    pos[1] = positions[3 * bc + 1];
    pos[2] = positions[3 * bc + 2];

    const int S[4]    = {128, 256, 512, 1024};
    const int QOFF[4] = {0, 49152, 245760, 1032192};

    // Precompute fractions and gather indices for all levels (ALU only).
    float frac[4][3];
    int   qix[4][3];
    #pragma unroll
    for (int L = 0; L < 4; L++) {
        const int s = S[L];
        const float sm1 = (float)s - 1.0f;
        int g[3];
        #pragma unroll
        for (int d = 0; d < 3; d++) {
            float x  = fmaf(pos[d], sm1, 0.5f);
            float gf = floorf(x);
            g[d] = (int)gf;
            frac[L][d] = x - gf;
        }
        #pragma unroll
        for (int pl = 0; pl < 3; pl++) {
            const int a1 = (pl + 1) % 3;   // c0=[0,1,2], c1=[1,2,0]
            qix[L][pl] = QOFF[L] + (pl * s + g[a1]) * s + g[pl];
        }
    }

    // Staggered pipeline: issue level L+1's gathers BEFORE consuming level L.
    uint4 qcur[3], qnext[3];
    #pragma unroll
    for (int pl = 0; pl < 3; pl++)
        qcur[pl] = __ldg(&g_quads[qix[0][pl]]);

    #pragma unroll
    for (int L = 0; L < 4; L++) {
        if (L < 3) {
            #pragma unroll
            for (int pl = 0; pl < 3; pl++)
                qnext[pl] = __ldg(&g_quads[qix[L + 1][pl]]);
        }

        float acc[3][2];
        #pragma unroll
        for (int pl = 0; pl < 3; pl++) {
            const int a1 = (pl + 1) % 3;
            const float f0 = frac[L][pl];
            const float f1 = frac[L][a1];
            uint4 qq = qcur[pl];
            float2 c00 = __half22float2(*reinterpret_cast<__half2*>(&qq.x));
            float2 c10 = __half22float2(*reinterpret_cast<__half2*>(&qq.y));
            float2 c01 = __half22float2(*reinterpret_cast<__half2*>(&qq.z));
            float2 c11 = __half22float2(*reinterpret_cast<__half2*>(&qq.w));

            const float w0 = 1.0f - f0;
            float l0x = fmaf(w0, c00.x, f0 * c10.x);
            float l0y = fmaf(w0, c00.y, f0 * c10.y);
            float l1x = fmaf(w0, c01.x, f0 * c11.x);
            float l1y = fmaf(w0, c01.y, f0 * c11.y);

            const float w1 = 1.0f - f1;
            acc[pl][0] = fmaf(w1, l0x, f1 * l1x);
            acc[pl][1] = fmaf(w1, l0y, f1 * l1y);
        }

        const float pr0 = acc[0][0] * acc[1][0] * acc[2][0];
        const float pr1 = acc[0][1] * acc[1][1] * acc[2][1];

        sbuf[warp][lane * 9 + L * 2 + 0] =
            make_float4(acc[0][0], acc[0][1], acc[1][0], acc[1][1]);
        sbuf[warp][lane * 9 + L * 2 + 1] =
            make_float4(acc[2][0], acc[2][1], pr0, pr1);

        #pragma unroll
        for (int pl = 0; pl < 3; pl++)
            qcur[pl] = qnext[pl];
    }

    __syncwarp();

    // Coalesced store phase, warp-scoped: this warp's 32 points = 4 KB
    // contiguous. Evict-first (__stcs) so the output stream does not evict
    // the quad table from L2.
    const int warpStart = blockStart + warp * 32;
    int vcount = B - warpStart;
    if (vcount > 32) vcount = 32;
    const int nf4 = vcount * 8;
    float4* __restrict__ of4 = (float4*)out + (size_t)warpStart * 8;

    #pragma unroll
    for (int it = 0; it < 8; it++) {
        int w4 = lane + it * 32;
        if (w4 < nf4) {
            int p  = w4 >> 3;
            int jj = w4 & 7;
            __stcs(&of4[w4], sbuf[warp][p * 9 + jj]);
        }
    }
}

extern "C" void kernel_launch(void* const* d_in, const int* in_sizes, int n_in,
                              void* d_out, int out_size) {
    const float* positions = (const float*)d_in[0];
    const float* table     = (const float*)d_in[1];
    float*       out       = (float*)d_out;

    int B = in_sizes[0] / 3;
    const int T = 256;

    build_quads_kernel<<<(NQUAD_TOTAL + T - 1) / T, T>>>(table);
    triplane_kernel<<<(B + T - 1) / T, T>>>(positions, out, B);
}

// round 17
// speedup vs baseline: 1.3467x; 1.0102x over previous
#include <cuda_runtime.h>
#include <cuda_fp16.h>

// Quad tables: per level, per plane, per (i,j) cell: the 4 bilinear corners
// (v00,v10,v01,v11) x 2 features, packed as 8 fp16 = 16 bytes = one LDG.128.
// Levels s = {128,256,512,1024}, entries = 3*s*s each.
// Quad offsets: L0=0, L1=49152, L2=245760, L3=1032192, total 4177920 (66.8 MB).
#define NQUAD_TOTAL 4177920
#define NQUAD_PAIRS (NQUAD_TOTAL / 2)
__device__ uint4 g_quads[NQUAD_TOTAL];

// Build kernel, 2 adjacent quads per thread: quads (2i, 2i+1) of one row
// share a corner column, so 6 float2 reads cover both (vs 8), and the two
// uint4 writes are address-adjacent (warp stores 1KB contiguous per step).
__global__ __launch_bounds__(256) void build_quads_kernel(const float* __restrict__ table)
{
    int t = blockIdx.x * blockDim.x + threadIdx.x;
    if (t >= NQUAD_PAIRS) return;

    // Pair-unit level boundaries: 24576 / 122880 / 516096 / 2088960.
    int ls, poff, fs;   // ls = log2(s), fs = log2(fac) = 10 - ls
    if      (t < 24576)   { ls = 7;  poff = 0;       fs = 3; }
    else if (t < 122880)  { ls = 8;  poff = 24576;   fs = 2; }
    else if (t < 516096)  { ls = 9;  poff = 122880;  fs = 1; }
    else                  { ls = 10; poff = 516096;  fs = 0; }

    int r  = t - poff;                       // pair index within level
    int pl = r >> (2 * ls - 1);              // per-plane pairs = s*s/2
    int r2 = r & ((1 << (2 * ls - 1)) - 1);
    int j  = r2 >> (ls - 1);                 // row (s/2 pairs per row)
    int ip = r2 & ((1 << (ls - 1)) - 1);     // pair within row
    int i  = ip << 1;                        // first quad's cell index

    int c0 = min(i << fs,       1023);
    int c1 = min((i + 1) << fs, 1023);
    int c2 = min((i + 2) << fs, 1023);
    int r0 = min(j << fs,       1023);
    int r1 = min((j + 1) << fs, 1023);

    const float2* __restrict__ tab = (const float2*)table + (pl << 20);
    float2 a0 = tab[(r0 << 10) + c0];   // row j : col i
    float2 a1 = tab[(r0 << 10) + c1];   // row j : col i+1
    float2 a2 = tab[(r0 << 10) + c2];   // row j : col i+2
    float2 b0 = tab[(r1 << 10) + c0];   // row j+1: col i
    float2 b1 = tab[(r1 << 10) + c1];
    float2 b2 = tab[(r1 << 10) + c2];

    __half2 ha0 = __floats2half2_rn(a0.x, a0.y);
    __half2 ha1 = __floats2half2_rn(a1.x, a1.y);
    __half2 ha2 = __floats2half2_rn(a2.x, a2.y);
    __half2 hb0 = __floats2half2_rn(b0.x, b0.y);
    __half2 hb1 = __floats2half2_rn(b1.x, b1.y);
    __half2 hb2 = __floats2half2_rn(b2.x, b2.y);

    unsigned ua0 = *reinterpret_cast<unsigned*>(&ha0);
    unsigned ua1 = *reinterpret_cast<unsigned*>(&ha1);
    unsigned ua2 = *reinterpret_cast<unsigned*>(&ha2);
    unsigned ub0 = *reinterpret_cast<unsigned*>(&hb0);
    unsigned ub1 = *reinterpret_cast<unsigned*>(&hb1);
    unsigned ub2 = *reinterpret_cast<unsigned*>(&hb2);

    uint4 q0, q1;                 // quad = (v00, v10, v01, v11)
    q0.x = ua0; q0.y = ua1; q0.z = ub0; q0.w = ub1;
    q1.x = ua1; q1.y = ua2; q1.z = ub1; q1.w = ub2;

    g_quads[2 * t + 0] = q0;      // default policy: keep table in L2
    g_quads[2 * t + 1] = q1;
}

// Main kernel: FROZEN at the R10 structure (191-195 us main, the measured
// local optimum: 12 divergent LDG.128 x 2.07 cyc/pt L1tex replay floor).
// Staggered 2-deep pipeline, 3 gathers per group, per-warp smem store
// staging, no block barrier, no min-blocks clause (regs<=40 squeeze
// measured ~1.8x slower).
__global__ __launch_bounds__(256) void triplane_kernel(
    const float* __restrict__ positions,
    float* __restrict__ out,
    int B)
{
    __shared__ float4 sbuf[8][32 * 9];   // per-warp staging, stride-9 padded

    const int warp = threadIdx.x >> 5;
    const int lane = threadIdx.x & 31;

    const int blockStart = blockIdx.x * 256;
    int b  = blockStart + threadIdx.x;
    int bc = b < B ? b : (B - 1);        // clamp so loads stay in-bounds

    float pos[3];
    pos[0] = positions[3 * bc + 0];
    pos[1] = positions[3 * bc + 1];
    pos[2] = positions[3 * bc + 2];

    const int S[4]    = {128, 256, 512, 1024};
    const int QOFF[4] = {0, 49152, 245760, 1032192};

    // Precompute fractions and gather indices for all levels (ALU only).
    float frac[4][3];
    int   qix[4][3];
    #pragma unroll
    for (int L = 0; L < 4; L++) {
        const int s = S[L];
        const float sm1 = (float)s - 1.0f;
        int g[3];
        #pragma unroll
        for (int d = 0; d < 3; d++) {
            float x  = fmaf(pos[d], sm1, 0.5f);
            float gf = floorf(x);
            g[d] = (int)gf;
            frac[L][d] = x - gf;
        }
        #pragma unroll
        for (int pl = 0; pl < 3; pl++) {
            const int a1 = (pl + 1) % 3;   // c0=[0,1,2], c1=[1,2,0]
            qix[L][pl] = QOFF[L] + (pl * s + g[a1]) * s + g[pl];
        }
    }

    // Staggered pipeline: issue level L+1's gathers BEFORE consuming level L.
    uint4 qcur[3], qnext[3];
    #pragma unroll
    for (int pl = 0; pl < 3; pl++)
        qcur[pl] = __ldg(&g_quads[qix[0][pl]]);

    #pragma unroll
    for (int L = 0; L < 4; L++) {
        if (L < 3) {
            #pragma unroll
            for (int pl = 0; pl < 3; pl++)
                qnext[pl] = __ldg(&g_quads[qix[L + 1][pl]]);
        }

        float acc[3][2];
        #pragma unroll
        for (int pl = 0; pl < 3; pl++) {
            const int a1 = (pl + 1) % 3;
            const float f0 = frac[L][pl];
            const float f1 = frac[L][a1];
            uint4 qq = qcur[pl];
            float2 c00 = __half22float2(*reinterpret_cast<__half2*>(&qq.x));
            float2 c10 = __half22float2(*reinterpret_cast<__half2*>(&qq.y));
            float2 c01 = __half22float2(*reinterpret_cast<__half2*>(&qq.z));
            float2 c11 = __half22float2(*reinterpret_cast<__half2*>(&qq.w));

            const float w0 = 1.0f - f0;
            float l0x = fmaf(w0, c00.x, f0 * c10.x);
            float l0y = fmaf(w0, c00.y, f0 * c10.y);
            float l1x = fmaf(w0, c01.x, f0 * c11.x);
            float l1y = fmaf(w0, c01.y, f0 * c11.y);

            const float w1 = 1.0f - f1;
            acc[pl][0] = fmaf(w1, l0x, f1 * l1x);
            acc[pl][1] = fmaf(w1, l0y, f1 * l1y);
        }

        const float pr0 = acc[0][0] * acc[1][0] * acc[2][0];
        const float pr1 = acc[0][1] * acc[1][1] * acc[2][1];

        sbuf[warp][lane * 9 + L * 2 + 0] =
            make_float4(acc[0][0], acc[0][1], acc[1][0], acc[1][1]);
        sbuf[warp][lane * 9 + L * 2 + 1] =
            make_float4(acc[2][0], acc[2][1], pr0, pr1);

        #pragma unroll
        for (int pl = 0; pl < 3; pl++)
            qcur[pl] = qnext[pl];
    }

    __syncwarp();

    // Coalesced store phase, warp-scoped: this warp's 32 points = 4 KB
    // contiguous. Evict-first (__stcs) so the output stream does not evict
    // the quad table from L2.
    const int warpStart = blockStart + warp * 32;
    int vcount = B - warpStart;
    if (vcount > 32) vcount = 32;
    const int nf4 = vcount * 8;
    float4* __restrict__ of4 = (float4*)out + (size_t)warpStart * 8;

    #pragma unroll
    for (int it = 0; it < 8; it++) {
        int w4 = lane + it * 32;
        if (w4 < nf4) {
            int p  = w4 >> 3;
            int jj = w4 & 7;
            __stcs(&of4[w4], sbuf[warp][p * 9 + jj]);
        }
    }
}

extern "C" void kernel_launch(void* const* d_in, const int* in_sizes, int n_in,
                              void* d_out, int out_size) {
    const float* positions = (const float*)d_in[0];
    const float* table     = (const float*)d_in[1];
    float*       out       = (float*)d_out;

    int B = in_sizes[0] / 3;
    const int T = 256;

    build_quads_kernel<<<(NQUAD_PAIRS + T - 1) / T, T>>>(table);
    triplane_kernel<<<(B + T - 1) / T, T>>>(positions, out, B);
}